// round 1
// baseline (speedup 1.0000x reference)
#include <cuda_runtime.h>
#include <math.h>

#define Nn 256
#define Ll 384
#define DMc 256
#define DPc 128
#define Hh 8
#define Dd 32
#define HD 256
#define NL (Nn*Ll)
#define LLc (Ll*Ll)
#define INV_SQRT_D 0.17677669529663687f

// ---------------- scratch (device globals; no allocation allowed) -------------
__device__ float g_qsw[Ll*HD];            // (i, h*32+d): q of row0, pre-scaled by 1/sqrt(D)
__device__ float g_mq[NL*HD];             // m @ wq
__device__ float g_k [NL*HD];             // (m @ wk) * 1/sqrt(D)
__device__ float g_v [NL*HD];             // m @ wv
__device__ float g_gate[NL*HD];           // sigmoid(m @ wg + bg)
__device__ float g_sw[NL*Hh];             // seq-weight logits -> weights (softmax over n)
__device__ float g_pb[Hh*LLc];            // pair bias [h][i][j]
__device__ float g_attn[Hh*LLc];          // attn logits -> probs [h][i][j]
__device__ float g_oatt[NL*HD];           // attention output before gate/out-proj

// ---------------- reductions -------------------------------------------------
__device__ __forceinline__ float warpSum(float v){
#pragma unroll
  for(int o=16;o;o>>=1) v += __shfl_xor_sync(0xffffffffu, v, o);
  return v;
}
__device__ __forceinline__ float warpMax(float v){
#pragma unroll
  for(int o=16;o;o>>=1) v = fmaxf(v, __shfl_xor_sync(0xffffffffu, v, o));
  return v;
}
// nw = number of warps in block (<=32). red must hold >= nw floats.
__device__ __forceinline__ float blockSum(float v, float* red, int nw){
  int t = threadIdx.x;
  v = warpSum(v);
  if((t&31)==0) red[t>>5] = v;
  __syncthreads();
  float s = 0.f;
  if(t < 32){
    s = (t < nw) ? red[t] : 0.f;
    s = warpSum(s);
    if(t==0) red[0] = s;
  }
  __syncthreads();
  s = red[0];
  __syncthreads();
  return s;
}
__device__ __forceinline__ float blockMax(float v, float* red, int nw){
  int t = threadIdx.x;
  v = warpMax(v);
  if((t&31)==0) red[t>>5] = v;
  __syncthreads();
  float s = -3.402823e38f;
  if(t < 32){
    s = (t < nw) ? red[t] : -3.402823e38f;
    s = warpMax(s);
    if(t==0) red[0] = s;
  }
  __syncthreads();
  s = red[0];
  __syncthreads();
  return s;
}

// ---------------- K0: qsw for MSA row 0 --------------------------------------
__global__ void k_qsw(const float* __restrict__ msa,
                      const float* __restrict__ lng, const float* __restrict__ lnb,
                      const float* __restrict__ swq, const float* __restrict__ sbq){
  int i = blockIdx.x, t = threadIdx.x;
  __shared__ float sm[DMc];
  __shared__ float red[32];
  float x = msa[(size_t)i*DMc + t];          // n = 0
  float mean = blockSum(x, red, 8) * (1.f/DMc);
  float d = x - mean;
  float var = blockSum(d*d, red, 8) * (1.f/DMc);
  float m = d * rsqrtf(var + 1e-5f) * lng[t] + lnb[t];
  sm[t] = m;
  __syncthreads();
  float acc = sbq[t];
#pragma unroll 8
  for(int r=0;r<DMc;r++) acc += sm[r]*swq[r*HD + t];
  g_qsw[i*HD + t] = acc * INV_SQRT_D;
}

// ---------------- K1: LN + 5 fused projections (16 rows/block) ---------------
__global__ __launch_bounds__(256) void k_proj(
  const float* __restrict__ msa,
  const float* __restrict__ lng, const float* __restrict__ lnb,
  const float* __restrict__ w_swk, const float* __restrict__ sbk,
  const float* __restrict__ wq, const float* __restrict__ wk,
  const float* __restrict__ wv, const float* __restrict__ wg,
  const float* __restrict__ bg)
{
  const int t = threadIdx.x;
  const int row0 = blockIdx.x * 16;
  __shared__ float sA[16][DMc];

  for(int idx=t; idx<16*DMc; idx+=256)
    ((float*)sA)[idx] = msa[(size_t)row0*DMc + idx];
  __syncthreads();

  { // LN: 16 threads per row
    int j = t >> 4, lg = t & 15;
    float a=0.f, b=0.f;
#pragma unroll
    for(int k=0;k<16;k++){ float x = sA[j][lg + 16*k]; a += x; b += x*x; }
#pragma unroll
    for(int o=8;o;o>>=1){
      a += __shfl_xor_sync(0xffffffffu, a, o);
      b += __shfl_xor_sync(0xffffffffu, b, o);
    }
    float mean = a*(1.f/DMc);
    float var  = b*(1.f/DMc) - mean*mean;
    float inv  = rsqrtf(var + 1e-5f);
#pragma unroll
    for(int k=0;k<16;k++){
      int r = lg + 16*k;
      float x = sA[j][r];
      sA[j][r] = (x-mean)*inv*lng[r] + lnb[r];
    }
  }
  __syncthreads();

  float acc0[16], acc1[16], acc2[16], acc3[16], acc4[16];
#pragma unroll
  for(int j=0;j<16;j++){ acc0[j]=0.f; acc1[j]=0.f; acc2[j]=0.f; acc3[j]=0.f; acc4[j]=0.f; }

  const float *p0 = w_swk + t, *p1 = wq + t, *p2 = wk + t, *p3 = wv + t, *p4 = wg + t;
  for(int r=0;r<DMc;r++){
    float w0 = p0[r*HD], w1 = p1[r*HD], w2 = p2[r*HD], w3 = p3[r*HD], w4 = p4[r*HD];
#pragma unroll
    for(int j=0;j<16;j++){
      float a = sA[j][r];
      acc0[j] += a*w0; acc1[j] += a*w1; acc2[j] += a*w2; acc3[j] += a*w3; acc4[j] += a*w4;
    }
  }

  const int h = t >> 5, lane = t & 31;
  const float kb = sbk[t], gb = bg[t];
#pragma unroll
  for(int j=0;j<16;j++){
    int row = row0 + j;
    int i = row % Ll;
    // sequence-weight logit: dot over all 256 channels via per-head warp reduce
    float ks = acc0[j] + kb;
    float c = ks * g_qsw[i*HD + t];
    c = warpSum(c);
    if(lane==0) g_sw[(size_t)row*Hh + h] = c;
    size_t o = (size_t)row*HD + t;
    g_mq[o]  = acc1[j];
    g_k[o]   = acc2[j] * INV_SQRT_D;
    g_v[o]   = acc3[j];
    g_gate[o]= 1.f/(1.f + expf(-(acc4[j] + gb)));
  }
}

// ---------------- K2: softmax over MSA depth n (N=256) -----------------------
__global__ void k_swsoftmax(){
  int b = blockIdx.x;            // L*H blocks
  int i = b >> 3, h = b & 7;
  int t = threadIdx.x;           // t = n
  __shared__ float red[32];
  size_t idx = ((size_t)t*Ll + i)*Hh + h;
  float x = g_sw[idx];
  float mx = blockMax(x, red, 8);
  float e = expf(x - mx);
  float s = blockSum(e, red, 8);
  g_sw[idx] = e / s;
}

// ---------------- K_pb: pair LN + bias projection ----------------------------
__global__ void k_pairbias(const float* __restrict__ pair,
                           const float* __restrict__ lnpg, const float* __restrict__ lnpb,
                           const float* __restrict__ wb){
  int p = blockIdx.x;            // L*L blocks, 128 threads
  int t = threadIdx.x;
  __shared__ float sp[DPc];
  __shared__ float red[128];
  __shared__ float sred[32];
  float x = pair[(size_t)p*DPc + t];
  float mean = blockSum(x, sred, 4) * (1.f/DPc);
  float d = x - mean;
  float var = blockSum(d*d, sred, 4) * (1.f/DPc);
  float m = d * rsqrtf(var + 1e-5f) * lnpg[t] + lnpb[t];
  sp[t] = m;
  __syncthreads();
  int hh = t & 7, g = t >> 3;
  float partial = 0.f;
#pragma unroll
  for(int k=0;k<8;k++){ int r = g*8 + k; partial += sp[r]*wb[r*Hh + hh]; }
  red[t] = partial;
  __syncthreads();
  for(int s=64; s>=8; s>>=1){ if(t<s) red[t] += red[t+s]; __syncthreads(); }
  if(t<8) g_pb[(size_t)t*LLc + p] = red[t];
}

// ---------------- K3: attn logits GEMM (64x64 tile, K = N*D = 8192) ----------
__global__ __launch_bounds__(256) void k_attn(){
  const int i0 = blockIdx.x*64, j0 = blockIdx.y*64, h = blockIdx.z;
  const int t = threadIdx.x, tx = t & 15, ty = t >> 4;
  __shared__ float As[32][68];
  __shared__ float Bs[32][68];
  float acc[4][4];
#pragma unroll
  for(int a=0;a<4;a++)
#pragma unroll
    for(int b=0;b<4;b++) acc[a][b]=0.f;

  const int lo = t & 31, q8 = t >> 5;
  for(int n=0;n<Nn;n++){
    const size_t rowA = (size_t)n*Ll + i0;
    const size_t rowB = (size_t)n*Ll + j0;
#pragma unroll
    for(int k=0;k<8;k++){
      int ii = q8 + 8*k;
      float swv = g_sw[(rowA+ii)*Hh + h];
      As[lo][ii] = g_mq[(rowA+ii)*HD + h*Dd + lo] * swv;
      Bs[lo][ii] = g_k [(rowB+ii)*HD + h*Dd + lo];
    }
    __syncthreads();
#pragma unroll
    for(int dd=0; dd<32; dd++){
      float4 a = *(const float4*)&As[dd][ty*4];
      float4 b = *(const float4*)&Bs[dd][tx*4];
      acc[0][0]+=a.x*b.x; acc[0][1]+=a.x*b.y; acc[0][2]+=a.x*b.z; acc[0][3]+=a.x*b.w;
      acc[1][0]+=a.y*b.x; acc[1][1]+=a.y*b.y; acc[1][2]+=a.y*b.z; acc[1][3]+=a.y*b.w;
      acc[2][0]+=a.z*b.x; acc[2][1]+=a.z*b.y; acc[2][2]+=a.z*b.z; acc[2][3]+=a.z*b.w;
      acc[3][0]+=a.w*b.x; acc[3][1]+=a.w*b.y; acc[3][2]+=a.w*b.z; acc[3][3]+=a.w*b.w;
    }
    __syncthreads();
  }
  const size_t base = (size_t)h*LLc;
#pragma unroll
  for(int ia=0; ia<4; ia++){
    int i = i0 + ty*4 + ia;
#pragma unroll
    for(int jb=0; jb<4; jb++){
      int j = j0 + tx*4 + jb;
      size_t o = base + (size_t)i*Ll + j;
      g_attn[o] = acc[ia][jb] + g_pb[o];
    }
  }
}

// ---------------- K4: softmax over j (length 384) ----------------------------
__global__ void k_attnsoftmax(){
  int b = blockIdx.x;            // H*L blocks, 128 threads
  int h = b / Ll, i = b % Ll;
  int t = threadIdx.x;
  __shared__ float red[32];
  size_t base = (size_t)h*LLc + (size_t)i*Ll;
  float x0 = g_attn[base + t];
  float x1 = g_attn[base + 128 + t];
  float x2 = g_attn[base + 256 + t];
  float mx = blockMax(fmaxf(x0, fmaxf(x1,x2)), red, 4);
  float e0 = expf(x0-mx), e1 = expf(x1-mx), e2 = expf(x2-mx);
  float s = blockSum(e0+e1+e2, red, 4);
  float inv = 1.f/s;
  g_attn[base + t]       = e0*inv;
  g_attn[base + 128 + t] = e1*inv;
  g_attn[base + 256 + t] = e2*inv;
}

// ---------------- K5a: attn @ V per head (64x64 tile, K = L = 384) -----------
__global__ __launch_bounds__(256) void k_pv(){
  const int i0 = blockIdx.x*64;
  const int c0 = blockIdx.y*64;        // columns over (n, d), d inner
  const int h = blockIdx.z;
  const int n0 = c0 >> 5;              // two n values per tile
  const int t = threadIdx.x, tx = t & 15, ty = t >> 4;
  __shared__ float As[32][68];
  __shared__ float Bs[32][68];
  float acc[4][4];
#pragma unroll
  for(int a=0;a<4;a++)
#pragma unroll
    for(int b=0;b<4;b++) acc[a][b]=0.f;

  const int lo = t & 31, q8 = t >> 5;
  const size_t attnBase = (size_t)h*LLc + (size_t)i0*Ll;
  for(int jc=0; jc<12; jc++){
    int jbase = jc*32;
#pragma unroll
    for(int k=0;k<8;k++){
      int q = q8 + 8*k;                // 0..63
      // A tile: P[h][i0+ii][jbase+lo]
      As[lo][q] = g_attn[attnBase + (size_t)q*Ll + jbase + lo];
      // B tile: V[(n0+nr)][jbase+jj][h*32+lo]
      int jj = q & 31, nr = q >> 5;
      Bs[jj][nr*32 + lo] = g_v[((size_t)(n0+nr)*Ll + jbase + jj)*HD + h*Dd + lo];
    }
    __syncthreads();
#pragma unroll
    for(int jj=0; jj<32; jj++){
      float4 a = *(const float4*)&As[jj][ty*4];
      float4 b = *(const float4*)&Bs[jj][tx*4];
      acc[0][0]+=a.x*b.x; acc[0][1]+=a.x*b.y; acc[0][2]+=a.x*b.z; acc[0][3]+=a.x*b.w;
      acc[1][0]+=a.y*b.x; acc[1][1]+=a.y*b.y; acc[1][2]+=a.y*b.z; acc[1][3]+=a.y*b.w;
      acc[2][0]+=a.z*b.x; acc[2][1]+=a.z*b.y; acc[2][2]+=a.z*b.z; acc[2][3]+=a.z*b.w;
      acc[3][0]+=a.w*b.x; acc[3][1]+=a.w*b.y; acc[3][2]+=a.w*b.z; acc[3][3]+=a.w*b.w;
    }
    __syncthreads();
  }
  const int col = tx*4;
  const int nr = col >> 5, dd0 = col & 31;
#pragma unroll
  for(int ia=0; ia<4; ia++){
    size_t o = ((size_t)(n0+nr)*Ll + (i0 + ty*4 + ia))*HD + h*Dd + dd0;
    float4 vv = make_float4(acc[ia][0], acc[ia][1], acc[ia][2], acc[ia][3]);
    *(float4*)(g_oatt + o) = vv;
  }
}

// ---------------- K5b: gate + output projection ------------------------------
__global__ __launch_bounds__(256) void k_out(const float* __restrict__ wo,
                                             const float* __restrict__ bo,
                                             float* __restrict__ out){
  const int t = threadIdx.x;
  const int row0 = blockIdx.x * 32;
  __shared__ float sA[32][HD];
  for(int idx=t; idx<32*HD; idx+=256){
    size_t o = (size_t)row0*HD + idx;
    ((float*)sA)[idx] = g_oatt[o] * g_gate[o];
  }
  __syncthreads();
  const int cg = t & 63, rq = t >> 6;
  float acc[8][4];
#pragma unroll
  for(int j=0;j<8;j++)
#pragma unroll
    for(int k=0;k<4;k++) acc[j][k]=0.f;

  for(int c=0;c<HD;c++){
    float4 w = *(const float4*)&wo[(size_t)c*DMc + cg*4];
#pragma unroll
    for(int j=0;j<8;j++){
      float a = sA[rq*8 + j][c];
      acc[j][0]+=a*w.x; acc[j][1]+=a*w.y; acc[j][2]+=a*w.z; acc[j][3]+=a*w.w;
    }
  }
  float4 b4 = *(const float4*)&bo[cg*4];
#pragma unroll
  for(int j=0;j<8;j++){
    float4 vv = make_float4(acc[j][0]+b4.x, acc[j][1]+b4.y, acc[j][2]+b4.z, acc[j][3]+b4.w);
    *(float4*)&out[((size_t)(row0 + rq*8 + j))*DMc + cg*4] = vv;
  }
}

// ---------------- launch -----------------------------------------------------
extern "C" void kernel_launch(void* const* d_in, const int* in_sizes, int n_in,
                              void* d_out, int out_size){
  const float* msa      = (const float*)d_in[0];
  const float* pair     = (const float*)d_in[1];
  const float* ln_msa_g = (const float*)d_in[2];
  const float* ln_msa_b = (const float*)d_in[3];
  const float* ln_pair_g= (const float*)d_in[4];
  const float* ln_pair_b= (const float*)d_in[5];
  const float* sw_wq    = (const float*)d_in[6];
  const float* sw_bq    = (const float*)d_in[7];
  const float* sw_wk    = (const float*)d_in[8];
  const float* sw_bk    = (const float*)d_in[9];
  const float* wq       = (const float*)d_in[10];
  const float* wk       = (const float*)d_in[11];
  const float* wv       = (const float*)d_in[12];
  const float* wb       = (const float*)d_in[13];
  const float* wg       = (const float*)d_in[14];
  const float* bg       = (const float*)d_in[15];
  const float* wo       = (const float*)d_in[16];
  const float* bo       = (const float*)d_in[17];
  float* out = (float*)d_out;

  k_qsw<<<Ll, 256>>>(msa, ln_msa_g, ln_msa_b, sw_wq, sw_bq);
  k_proj<<<NL/16, 256>>>(msa, ln_msa_g, ln_msa_b, sw_wk, sw_bk, wq, wk, wv, wg, bg);
  k_swsoftmax<<<Ll*Hh, 256>>>();
  k_pairbias<<<LLc, 128>>>(pair, ln_pair_g, ln_pair_b, wb);
  k_attn<<<dim3(Ll/64, Ll/64, Hh), 256>>>();
  k_attnsoftmax<<<Hh*Ll, 128>>>();
  k_pv<<<dim3(Ll/64, (Nn*Dd)/64, Hh), 256>>>();
  k_out<<<NL/32, 256>>>(wo, bo, out);
}

// round 3
// speedup vs baseline: 1.7751x; 1.7751x over previous
#include <cuda_runtime.h>
#include <math.h>

#define Nn 256
#define Ll 384
#define DMc 256
#define Hh 8
#define Dd 32
#define HD 256
#define NL (Nn*Ll)
#define LLc (Ll*Ll)
#define INV_SQRT_D 0.17677669529663687f

// ---------------- scratch (device globals; no allocation allowed) -------------
__device__ float g_qsw[Ll*HD];
__device__ float g_ksw[NL*HD];
__device__ float g_mq[NL*HD];
__device__ float g_k [NL*HD];
__device__ float g_v [NL*HD];
__device__ float g_gate[NL*HD];
__device__ float g_sw[NL*Hh];
__device__ float g_pb[Hh*LLc];
__device__ float g_attn[Hh*LLc];
__device__ float g_oatt[NL*HD];

// ---------------- helpers ----------------------------------------------------
__device__ __forceinline__ unsigned f2tf(float x){
  unsigned u; asm("cvt.rna.tf32.f32 %0, %1;" : "=r"(u) : "f"(x)); return u;
}
__device__ __forceinline__ void mma_tf32(float c[4], const unsigned a[4], const unsigned b[2]){
  asm volatile("mma.sync.aligned.m16n8k8.row.col.f32.tf32.tf32.f32 "
    "{%0,%1,%2,%3},{%4,%5,%6,%7},{%8,%9},{%0,%1,%2,%3};"
    : "+f"(c[0]),"+f"(c[1]),"+f"(c[2]),"+f"(c[3])
    : "r"(a[0]),"r"(a[1]),"r"(a[2]),"r"(a[3]),"r"(b[0]),"r"(b[1]));
}
__device__ __forceinline__ float warpSum(float v){
#pragma unroll
  for(int o=16;o;o>>=1) v += __shfl_xor_sync(0xffffffffu, v, o);
  return v;
}
__device__ __forceinline__ float warpMax(float v){
#pragma unroll
  for(int o=16;o;o>>=1) v = fmaxf(v, __shfl_xor_sync(0xffffffffu, v, o));
  return v;
}
__device__ __forceinline__ float blockSum(float v, float* red, int nw){
  int t = threadIdx.x;
  v = warpSum(v);
  if((t&31)==0) red[t>>5] = v;
  __syncthreads();
  float s = 0.f;
  if(t < 32){
    s = (t < nw) ? red[t] : 0.f;
    s = warpSum(s);
    if(t==0) red[0] = s;
  }
  __syncthreads();
  s = red[0];
  __syncthreads();
  return s;
}
__device__ __forceinline__ float blockMax(float v, float* red, int nw){
  int t = threadIdx.x;
  v = warpMax(v);
  if((t&31)==0) red[t>>5] = v;
  __syncthreads();
  float s = -3.402823e38f;
  if(t < 32){
    s = (t < nw) ? red[t] : -3.402823e38f;
    s = warpMax(s);
    if(t==0) red[0] = s;
  }
  __syncthreads();
  s = red[0];
  __syncthreads();
  return s;
}

// ---------------- K0: qsw for MSA row 0 --------------------------------------
__global__ void k_qsw(const float* __restrict__ msa,
                      const float* __restrict__ lng, const float* __restrict__ lnb,
                      const float* __restrict__ swq, const float* __restrict__ sbq){
  int i = blockIdx.x, t = threadIdx.x;
  __shared__ float sm[DMc];
  __shared__ float red[32];
  float x = msa[(size_t)i*DMc + t];          // n = 0
  float mean = blockSum(x, red, 8) * (1.f/DMc);
  float d = x - mean;
  float var = blockSum(d*d, red, 8) * (1.f/DMc);
  float m = d * rsqrtf(var + 1e-5f) * lng[t] + lnb[t];
  sm[t] = m;
  __syncthreads();
  float acc = sbq[t];
#pragma unroll 8
  for(int r=0;r<DMc;r++) acc += sm[r]*swq[r*HD + t];
  g_qsw[i*HD + t] = acc * INV_SQRT_D;
}

// ---------------- K1: LN + 5 projections via tf32 MMA ------------------------
#define PROJ_SMEM ((128*260 + 256*68 + 128+128+256+256)*4)
__global__ __launch_bounds__(512) void k_proj(
  const float* __restrict__ msa,
  const float* __restrict__ lng, const float* __restrict__ lnb,
  const float* __restrict__ w0, const float* __restrict__ w1,
  const float* __restrict__ w2, const float* __restrict__ w3,
  const float* __restrict__ w4,
  const float* __restrict__ sbk, const float* __restrict__ bg)
{
  extern __shared__ unsigned dsm[];
  unsigned (*sA)[260] = (unsigned(*)[260])dsm;               // 128 x 256 tf32
  unsigned (*sB)[68]  = (unsigned(*)[68])(dsm + 128*260);    // 256(k) x 64(n)
  float* smean = (float*)(dsm + 128*260 + 256*68);
  float* sinv  = smean + 128;
  float* sG    = sinv + 128;
  float* sBt   = sG + 256;

  const int t = threadIdx.x;
  const size_t row0 = (size_t)blockIdx.x * 128;

  if(t < 256){ sG[t] = lng[t]; sBt[t] = lnb[t]; }
  {
    int j = t>>2, q = t&3;
    const float* rp = msa + (row0 + j)*DMc + q*64;
    float s=0.f, ss=0.f;
#pragma unroll
    for(int f=0; f<16; f++){
      float4 x = *(const float4*)(rp + f*4);
      s  += x.x+x.y+x.z+x.w;
      ss += x.x*x.x + x.y*x.y + x.z*x.z + x.w*x.w;
    }
#pragma unroll
    for(int o=1;o<4;o<<=1){
      s  += __shfl_xor_sync(0xffffffffu, s, o);
      ss += __shfl_xor_sync(0xffffffffu, ss, o);
    }
    float mean = s*(1.f/256.f);
    float var  = ss*(1.f/256.f) - mean*mean;
    if(q==0){ smean[j]=mean; sinv[j]=rsqrtf(var+1e-5f); }
  }
  __syncthreads();
#pragma unroll
  for(int p=0;p<16;p++){
    int lin = p*512 + t;
    int r = lin>>6, f = lin&63;
    float4 x = *(const float4*)(msa + (row0+r)*DMc + f*4);
    float mean = smean[r], inv = sinv[r];
    int c = f*4;
    sA[r][c+0] = f2tf((x.x-mean)*inv*sG[c+0]+sBt[c+0]);
    sA[r][c+1] = f2tf((x.y-mean)*inv*sG[c+1]+sBt[c+1]);
    sA[r][c+2] = f2tf((x.z-mean)*inv*sG[c+2]+sBt[c+2]);
    sA[r][c+3] = f2tf((x.w-mean)*inv*sG[c+3]+sBt[c+3]);
  }

  const int w = t>>5, lane = t&31;
  const int wm = w>>1, wn = w&1;
  const int qr = lane>>2, ql = lane&3;

  for(int nc=0; nc<20; nc++){
    const int mi = nc>>2;
    const int off = (nc&3)*64;
    const float* W = (mi==0)?w0:(mi==1)?w1:(mi==2)?w2:(mi==3)?w3:w4;
    __syncthreads();
#pragma unroll
    for(int p=0;p<8;p++){
      int lin = p*512 + t;
      int r = lin>>4, f = lin&15;
      float4 x = *(const float4*)(W + (size_t)r*HD + off + f*4);
      int c = f*4;
      sB[r][c+0]=f2tf(x.x); sB[r][c+1]=f2tf(x.y);
      sB[r][c+2]=f2tf(x.z); sB[r][c+3]=f2tf(x.w);
    }
    __syncthreads();
    float acc[4][4];
#pragma unroll
    for(int i1=0;i1<4;i1++)
#pragma unroll
      for(int i2=0;i2<4;i2++) acc[i1][i2]=0.f;
#pragma unroll 4
    for(int ks=0; ks<32; ks++){
      int k0 = ks*8;
      unsigned a[4];
      int R = wm*16;
      a[0]=sA[R+qr  ][k0+ql  ]; a[1]=sA[R+qr+8][k0+ql  ];
      a[2]=sA[R+qr  ][k0+ql+4]; a[3]=sA[R+qr+8][k0+ql+4];
      unsigned b[4][2];
#pragma unroll
      for(int bn=0;bn<4;bn++){
        int n0 = wn*32 + bn*8;
        b[bn][0]=sB[k0+ql  ][n0+qr];
        b[bn][1]=sB[k0+ql+4][n0+qr];
      }
#pragma unroll
      for(int bn=0;bn<4;bn++) mma_tf32(acc[bn], a, b[bn]);
    }
    int rowa = (int)row0 + wm*16 + qr;
#pragma unroll
    for(int bn=0;bn<4;bn++){
      int cg = nc*64 + wn*32 + bn*8 + 2*ql;
      int c2 = cg & 255;
      size_t o0 = (size_t)rowa*HD + c2;
      size_t o1 = (size_t)(rowa+8)*HD + c2;
      float v0=acc[bn][0], v1=acc[bn][1], v2=acc[bn][2], v3=acc[bn][3];
      if(mi==0){
        float b0v = sbk[c2], b1v = sbk[c2+1];
        *(float2*)(g_ksw+o0) = make_float2(v0+b0v, v1+b1v);
        *(float2*)(g_ksw+o1) = make_float2(v2+b0v, v3+b1v);
      } else if(mi==1){
        *(float2*)(g_mq+o0) = make_float2(v0, v1);
        *(float2*)(g_mq+o1) = make_float2(v2, v3);
      } else if(mi==2){
        *(float2*)(g_k+o0) = make_float2(v0*INV_SQRT_D, v1*INV_SQRT_D);
        *(float2*)(g_k+o1) = make_float2(v2*INV_SQRT_D, v3*INV_SQRT_D);
      } else if(mi==3){
        *(float2*)(g_v+o0) = make_float2(v0, v1);
        *(float2*)(g_v+o1) = make_float2(v2, v3);
      } else {
        float b0v = bg[c2], b1v = bg[c2+1];
        *(float2*)(g_gate+o0) = make_float2(1.f/(1.f+expf(-(v0+b0v))), 1.f/(1.f+expf(-(v1+b1v))));
        *(float2*)(g_gate+o1) = make_float2(1.f/(1.f+expf(-(v2+b0v))), 1.f/(1.f+expf(-(v3+b1v))));
      }
    }
  }
}

// ---------------- K2: seq-weight logits + softmax over n ---------------------
__global__ __launch_bounds__(256) void k_swl(){
  __shared__ float sq[256];
  __shared__ float sL[256][9];
  __shared__ float smx[8], srs[8];
  int i = blockIdx.x, t = threadIdx.x;
  sq[t] = g_qsw[i*HD + t];
  __syncthreads();
  const float* kr = g_ksw + ((size_t)t*Ll + i)*HD;
  float lg[8];
#pragma unroll
  for(int h=0;h<8;h++){
    float s = 0.f;
#pragma unroll
    for(int f=0; f<8; f++){
      float4 kx = *(const float4*)(kr + h*32 + f*4);
      int c = h*32 + f*4;
      s += kx.x*sq[c] + kx.y*sq[c+1] + kx.z*sq[c+2] + kx.w*sq[c+3];
    }
    lg[h]=s; sL[t][h]=s;
  }
  __syncthreads();
  {
    int w = t>>5, lane = t&31;
    float mx = -3.402823e38f;
#pragma unroll
    for(int e=0;e<8;e++) mx = fmaxf(mx, sL[lane*8+e][w]);
    mx = warpMax(mx);
    float s = 0.f;
#pragma unroll
    for(int e=0;e<8;e++) s += expf(sL[lane*8+e][w]-mx);
    s = warpSum(s);
    if(lane==0){ smx[w]=mx; srs[w]=1.f/s; }
  }
  __syncthreads();
  size_t o = ((size_t)t*Ll + i)*Hh;
#pragma unroll
  for(int h=0;h<8;h++) g_sw[o+h] = expf(lg[h]-smx[h])*srs[h];
}

// ---------------- K3: pair LN + bias projection (warp per pair) --------------
__global__ __launch_bounds__(256) void k_pb2(const float* __restrict__ pair,
    const float* __restrict__ lnpg, const float* __restrict__ lnpb,
    const float* __restrict__ wb){
  __shared__ float swb[128*9];
  int t = threadIdx.x;
  for(int u=t; u<1024; u+=256){ swb[(u>>3)*9 + (u&7)] = wb[u]; }
  __syncthreads();
  int w = t>>5, lane = t&31;
  size_t p = (size_t)blockIdx.x*8 + w;
  const float* pr = pair + p*128;
  float4 x = *(const float4*)(pr + lane*4);
  float s  = x.x+x.y+x.z+x.w;
  float ss = x.x*x.x+x.y*x.y+x.z*x.z+x.w*x.w;
  s = warpSum(s); ss = warpSum(ss);
  float mean = s*(1.f/128.f);
  float inv = rsqrtf(ss*(1.f/128.f)-mean*mean + 1e-5f);
  int c = lane*4;
  float m0=(x.x-mean)*inv*lnpg[c+0]+lnpb[c+0];
  float m1=(x.y-mean)*inv*lnpg[c+1]+lnpb[c+1];
  float m2=(x.z-mean)*inv*lnpg[c+2]+lnpb[c+2];
  float m3=(x.w-mean)*inv*lnpg[c+3]+lnpb[c+3];
  float mine=0.f;
#pragma unroll
  for(int h=0;h<8;h++){
    float pt = m0*swb[(c+0)*9+h] + m1*swb[(c+1)*9+h]
             + m2*swb[(c+2)*9+h] + m3*swb[(c+3)*9+h];
    pt = warpSum(pt);
    if(lane==h) mine = pt;
  }
  if(lane<8) g_pb[(size_t)lane*LLc + p] = mine;
}

// ---------------- K4: attn logits via tf32 MMA -------------------------------
__global__ __launch_bounds__(256) void k_attn(){
  __shared__ unsigned sA[128][36];
  __shared__ unsigned sB[64][36];
  const int h = blockIdx.z;
  const int i0 = blockIdx.x*128, j0 = blockIdx.y*64;
  const int t = threadIdx.x, w = t>>5, lane = t&31;
  const int wm = w>>1, wn = w&1;
  const int qr = lane>>2, ql = lane&3;
  float acc[2][4][4];
#pragma unroll
  for(int am=0;am<2;am++)
#pragma unroll
    for(int bn=0;bn<4;bn++)
#pragma unroll
      for(int e=0;e<4;e++) acc[am][bn][e]=0.f;

  for(int n=0;n<Nn;n++){
    __syncthreads();
    const size_t baseA = ((size_t)n*Ll + i0)*HD + h*Dd;
#pragma unroll
    for(int p=0;p<4;p++){
      int u = p*256 + t;
      int r = u>>3, f = u&7;
      float4 x = *(const float4*)(g_mq + baseA + (size_t)r*HD + f*4);
      float sv = g_sw[((size_t)n*Ll + i0 + r)*Hh + h];
      int c = f*4;
      sA[r][c+0]=f2tf(x.x*sv); sA[r][c+1]=f2tf(x.y*sv);
      sA[r][c+2]=f2tf(x.z*sv); sA[r][c+3]=f2tf(x.w*sv);
    }
    const size_t baseB = ((size_t)n*Ll + j0)*HD + h*Dd;
#pragma unroll
    for(int p=0;p<2;p++){
      int u = p*256 + t;
      int r = u>>3, f = u&7;
      float4 x = *(const float4*)(g_k + baseB + (size_t)r*HD + f*4);
      int c = f*4;
      sB[r][c+0]=f2tf(x.x); sB[r][c+1]=f2tf(x.y);
      sB[r][c+2]=f2tf(x.z); sB[r][c+3]=f2tf(x.w);
    }
    __syncthreads();
#pragma unroll
    for(int ks=0;ks<4;ks++){
      int k0 = ks*8;
      unsigned a[2][4], b[4][2];
#pragma unroll
      for(int am=0;am<2;am++){
        int R = wm*32 + am*16;
        a[am][0]=sA[R+qr  ][k0+ql  ]; a[am][1]=sA[R+qr+8][k0+ql  ];
        a[am][2]=sA[R+qr  ][k0+ql+4]; a[am][3]=sA[R+qr+8][k0+ql+4];
      }
#pragma unroll
      for(int bn=0;bn<4;bn++){
        int n0 = wn*32 + bn*8;
        b[bn][0]=sB[n0+qr][k0+ql];
        b[bn][1]=sB[n0+qr][k0+ql+4];
      }
#pragma unroll
      for(int am=0;am<2;am++)
#pragma unroll
        for(int bn=0;bn<4;bn++) mma_tf32(acc[am][bn], a[am], b[bn]);
    }
  }
  const size_t hb = (size_t)h*LLc;
#pragma unroll
  for(int am=0;am<2;am++){
    int i = i0 + wm*32 + am*16 + qr;
#pragma unroll
    for(int bn=0;bn<4;bn++){
      int j = j0 + wn*32 + bn*8 + 2*ql;
      size_t o = hb + (size_t)i*Ll + j;
      float2 pb0 = *(const float2*)(g_pb+o);
      *(float2*)(g_attn+o) = make_float2(acc[am][bn][0]+pb0.x, acc[am][bn][1]+pb0.y);
      size_t o2 = o + (size_t)8*Ll;
      float2 pb1 = *(const float2*)(g_pb+o2);
      *(float2*)(g_attn+o2) = make_float2(acc[am][bn][2]+pb1.x, acc[am][bn][3]+pb1.y);
    }
  }
}

// ---------------- K5: softmax over j ------------------------------------------
__global__ void k_attnsoftmax(){
  int b = blockIdx.x;
  int h = b / Ll, i = b % Ll;
  int t = threadIdx.x;
  __shared__ float red[32];
  size_t base = (size_t)h*LLc + (size_t)i*Ll;
  float x0 = g_attn[base + t];
  float x1 = g_attn[base + 128 + t];
  float x2 = g_attn[base + 256 + t];
  float mx = blockMax(fmaxf(x0, fmaxf(x1,x2)), red, 4);
  float e0 = expf(x0-mx), e1 = expf(x1-mx), e2 = expf(x2-mx);
  float s = blockSum(e0+e1+e2, red, 4);
  float inv = 1.f/s;
  g_attn[base + t]       = e0*inv;
  g_attn[base + 128 + t] = e1*inv;
  g_attn[base + 256 + t] = e2*inv;
}

// ---------------- K6: P @ V via tf32 MMA -------------------------------------
__global__ __launch_bounds__(256) void k_pv(){
  __shared__ unsigned sA[128][36];
  __shared__ unsigned sB[128][36];
  const int h = blockIdx.z;
  const int i0 = blockIdx.x*128;
  const int n0 = blockIdx.y*4;
  const int t = threadIdx.x, w = t>>5, lane = t&31;
  const int wm = w>>1, wn = w&1;
  const int qr = lane>>2, ql = lane&3;
  float acc[2][8][4];
#pragma unroll
  for(int am=0;am<2;am++)
#pragma unroll
    for(int bn=0;bn<8;bn++)
#pragma unroll
      for(int e=0;e<4;e++) acc[am][bn][e]=0.f;

  const size_t attnBase = (size_t)h*LLc + (size_t)i0*Ll;
  for(int jc=0;jc<12;jc++){
    int j0 = jc*32;
    __syncthreads();
#pragma unroll
    for(int p=0;p<4;p++){
      int u = p*256 + t;
      int r = u>>3, f = u&7;
      float4 x = *(const float4*)(g_attn + attnBase + (size_t)r*Ll + j0 + f*4);
      int c = f*4;
      sA[r][c+0]=f2tf(x.x); sA[r][c+1]=f2tf(x.y);
      sA[r][c+2]=f2tf(x.z); sA[r][c+3]=f2tf(x.w);
    }
#pragma unroll
    for(int p=0;p<4;p++){
      int u = p*256 + t;
      int nv = u>>8, jj = (u>>3)&31, f = u&7;
      float4 x = *(const float4*)(g_v + ((size_t)(n0+nv)*Ll + j0+jj)*HD + h*Dd + f*4);
      int c = nv*32 + f*4;
      sB[c+0][jj]=f2tf(x.x); sB[c+1][jj]=f2tf(x.y);
      sB[c+2][jj]=f2tf(x.z); sB[c+3][jj]=f2tf(x.w);
    }
    __syncthreads();
#pragma unroll
    for(int ks=0;ks<4;ks++){
      int k0 = ks*8;
      unsigned a[2][4], b[8][2];
#pragma unroll
      for(int am=0;am<2;am++){
        int R = wm*32 + am*16;
        a[am][0]=sA[R+qr  ][k0+ql  ]; a[am][1]=sA[R+qr+8][k0+ql  ];
        a[am][2]=sA[R+qr  ][k0+ql+4]; a[am][3]=sA[R+qr+8][k0+ql+4];
      }
#pragma unroll
      for(int bn=0;bn<8;bn++){
        int nf = wn*64 + bn*8;
        b[bn][0]=sB[nf+qr][k0+ql];
        b[bn][1]=sB[nf+qr][k0+ql+4];
      }
#pragma unroll
      for(int am=0;am<2;am++)
#pragma unroll
        for(int bn=0;bn<8;bn++) mma_tf32(acc[am][bn], a[am], b[bn]);
    }
  }
#pragma unroll
  for(int am=0;am<2;am++){
    int i = i0 + wm*32 + am*16 + qr;
#pragma unroll
    for(int bn=0;bn<8;bn++){
      int col = wn*64 + bn*8 + 2*ql;
      int nv = col>>5, dd = col&31;
      size_t o = ((size_t)(n0+nv)*Ll + i)*HD + h*Dd + dd;
      *(float2*)(g_oatt+o) = make_float2(acc[am][bn][0], acc[am][bn][1]);
      size_t o2 = o + (size_t)8*HD;
      *(float2*)(g_oatt+o2) = make_float2(acc[am][bn][2], acc[am][bn][3]);
    }
  }
}

// ---------------- K7: gate + out projection via tf32 MMA ---------------------
#define OUT_SMEM ((64*260 + 256*68)*4)
__global__ __launch_bounds__(256) void k_out(const float* __restrict__ wo,
                                             const float* __restrict__ bo,
                                             float* __restrict__ out){
  extern __shared__ unsigned dsm[];
  unsigned (*sA)[260] = (unsigned(*)[260])dsm;             // 64 x 256
  unsigned (*sB)[68]  = (unsigned(*)[68])(dsm + 64*260);   // 256 x 64
  const int t = threadIdx.x;
  const size_t row0 = (size_t)blockIdx.x*64;
  const int w = t>>5, lane = t&31;
  const int wm = w>>1, wn = w&1;
  const int qr = lane>>2, ql = lane&3;
#pragma unroll
  for(int p=0;p<16;p++){
    int lin = p*256 + t;
    int r = lin>>6, f = lin&63;
    size_t o = (row0+r)*HD + f*4;
    float4 a = *(const float4*)(g_oatt + o);
    float4 g = *(const float4*)(g_gate + o);
    int c = f*4;
    sA[r][c+0]=f2tf(a.x*g.x); sA[r][c+1]=f2tf(a.y*g.y);
    sA[r][c+2]=f2tf(a.z*g.z); sA[r][c+3]=f2tf(a.w*g.w);
  }
  __syncthreads();
  for(int nc=0; nc<4; nc++){
#pragma unroll
    for(int p=0;p<16;p++){
      int lin = p*256 + t;
      int r = lin>>4, f = lin&15;
      float4 x = *(const float4*)(wo + (size_t)r*DMc + nc*64 + f*4);
      int c = f*4;
      sB[r][c+0]=f2tf(x.x); sB[r][c+1]=f2tf(x.y);
      sB[r][c+2]=f2tf(x.z); sB[r][c+3]=f2tf(x.w);
    }
    __syncthreads();
    float acc[4][4];
#pragma unroll
    for(int i1=0;i1<4;i1++)
#pragma unroll
      for(int i2=0;i2<4;i2++) acc[i1][i2]=0.f;
#pragma unroll 4
    for(int ks=0; ks<32; ks++){
      int k0 = ks*8;
      unsigned a[4];
      int R = wm*16;
      a[0]=sA[R+qr  ][k0+ql  ]; a[1]=sA[R+qr+8][k0+ql  ];
      a[2]=sA[R+qr  ][k0+ql+4]; a[3]=sA[R+qr+8][k0+ql+4];
      unsigned b[4][2];
#pragma unroll
      for(int bn=0;bn<4;bn++){
        int n0 = wn*32 + bn*8;
        b[bn][0]=sB[k0+ql  ][n0+qr];
        b[bn][1]=sB[k0+ql+4][n0+qr];
      }
#pragma unroll
      for(int bn=0;bn<4;bn++) mma_tf32(acc[bn], a, b[bn]);
    }
    int rowa = (int)row0 + wm*16 + qr;
#pragma unroll
    for(int bn=0;bn<4;bn++){
      int cg = nc*64 + wn*32 + bn*8 + 2*ql;
      float2 b2 = *(const float2*)(bo + cg);
      *(float2*)(out + (size_t)rowa*DMc + cg) =
          make_float2(acc[bn][0]+b2.x, acc[bn][1]+b2.y);
      *(float2*)(out + (size_t)(rowa+8)*DMc + cg) =
          make_float2(acc[bn][2]+b2.x, acc[bn][3]+b2.y);
    }
    __syncthreads();
  }
}

// ---------------- launch -----------------------------------------------------
extern "C" void kernel_launch(void* const* d_in, const int* in_sizes, int n_in,
                              void* d_out, int out_size){
  const float* msa      = (const float*)d_in[0];
  const float* pair     = (const float*)d_in[1];
  const float* ln_msa_g = (const float*)d_in[2];
  const float* ln_msa_b = (const float*)d_in[3];
  const float* ln_pair_g= (const float*)d_in[4];
  const float* ln_pair_b= (const float*)d_in[5];
  const float* sw_wq    = (const float*)d_in[6];
  const float* sw_bq    = (const float*)d_in[7];
  const float* sw_wk    = (const float*)d_in[8];
  const float* sw_bk    = (const float*)d_in[9];
  const float* wq       = (const float*)d_in[10];
  const float* wk       = (const float*)d_in[11];
  const float* wv       = (const float*)d_in[12];
  const float* wb       = (const float*)d_in[13];
  const float* wg       = (const float*)d_in[14];
  const float* bg       = (const float*)d_in[15];
  const float* wo       = (const float*)d_in[16];
  const float* bo       = (const float*)d_in[17];
  float* out = (float*)d_out;

  cudaFuncSetAttribute(k_proj, cudaFuncAttributeMaxDynamicSharedMemorySize, PROJ_SMEM);
  cudaFuncSetAttribute(k_out,  cudaFuncAttributeMaxDynamicSharedMemorySize, OUT_SMEM);

  k_qsw<<<Ll, 256>>>(msa, ln_msa_g, ln_msa_b, sw_wq, sw_bq);
  k_proj<<<NL/128, 512, PROJ_SMEM>>>(msa, ln_msa_g, ln_msa_b,
                                     sw_wk, wq, wk, wv, wg, sw_bk, bg);
  k_swl<<<Ll, 256>>>();
  k_pb2<<<LLc/8, 256>>>(pair, ln_pair_g, ln_pair_b, wb);
  k_attn<<<dim3(3,6,8), 256>>>();
  k_attnsoftmax<<<Hh*Ll, 128>>>();
  k_pv<<<dim3(3,64,8), 256>>>();   // 256 n-rows / 4 per block = 64
  k_out<<<NL/64, 256, OUT_SMEM>>>(wo, bo, out);
}